// round 15
// baseline (speedup 1.0000x reference)
#include <cuda_runtime.h>
#include <cuda_bf16.h>
#include <math.h>
#include <cstdint>

#define BATCH   16384
#define CCH     72
#define HH      34
#define SAMP    2448
#define OSAMP   2856
#define TB      8             /* samples per tile */
#define NT      2048          /* tiles */
#define GRID3   148           /* persistent blocks (1 per SM) */
#define BT      288
#define RED_BLOCKS 64
#define RED_PER    256
#define WB_BLOCKS  24
#define BN_COUNT   (16384.0f*34.0f)
#define BN_EPS_F   1e-5f

/* k3 smem layout (bytes) */
#define OFF_BC  0             /* 72 f   */
#define OFF_SCX 288           /* 72 f   */
#define OFF_XC  576           /* 72 i   */
#define OFF_ML  864           /* 2 x 48 f (double-buffered) */
#define OFF_RAW 1280          /* 8*2448 f = 78336 B */
#define OFF_A   79616         /* 18*9*128 u32 = 82944 B */
#define OFF_B   162560        /* 3456 u32 = 13824 B */
#define SMEM_K3 176384
#define OFF_D   OFF_A
#define DSTRIDE 50

__device__ float g_mult[BATCH*6];
__device__ float g_part[BATCH*144];
__device__ float g_part2[RED_BLOCKS*144];
__device__ float g_ss[144];
__device__ unsigned int g_Bf[3456];

__device__ __forceinline__ float sigmoidf_(float z) {
    return 1.0f / (1.0f + __expf(-z));
}
__device__ __forceinline__ unsigned int f2tf32(float v) {
    unsigned int u;
    asm("cvt.rna.tf32.f32 %0, %1;" : "=r"(u) : "f"(v));
    return u;
}

#define MMAT32(d, a, bx, by) \
    asm volatile("mma.sync.aligned.m16n8k8.row.col.f32.tf32.tf32.f32 " \
        "{%0,%1,%2,%3}, {%4,%5,%6,%7}, {%8,%9}, {%0,%1,%2,%3};" \
        : "+f"((d)[0]), "+f"((d)[1]), "+f"((d)[2]), "+f"((d)[3]) \
        : "r"((a).x), "r"((a).y), "r"((a).z), "r"((a).w), "r"(bx), "r"(by))

#define CP_ASYNC16(dst_u32, src) \
    asm volatile("cp.async.cg.shared.global [%0], [%1], 16;" :: "r"(dst_u32), "l"(src))
#define CP_COMMIT() asm volatile("cp.async.commit_group;" ::: "memory")
#define CP_WAIT0()  asm volatile("cp.async.wait_group 0;" ::: "memory")

// ---------------------------------------------------------------------------
// K1: per-sample gates + BN partial sums (read-only)
// ---------------------------------------------------------------------------
__global__ void __launch_bounds__(128) k1_stats(
    const float* __restrict__ x, const float* __restrict__ fcw,
    const float* __restrict__ fcb)
{
    __shared__ float xs[SAMP];
    __shared__ float ws[HH];
    __shared__ float s1[CCH], s2[CCH], sw[CCH];
    __shared__ float lin[6];

    const int b = blockIdx.x, tid = threadIdx.x;
    const float4* xin4 = (const float4*)(x + (size_t)b * SAMP);
    float4* xs4 = (float4*)xs;
    #pragma unroll
    for (int i = tid; i < SAMP/4; i += 128) xs4[i] = xin4[i];
    if (tid < HH) ws[tid] = fcw[tid];
    __syncthreads();

    if (tid < CCH) {
        float a1 = 0.f, a2 = 0.f, aw = 0.f;
        const float* row = xs + tid * HH;
        #pragma unroll
        for (int h = 0; h < HH; h++) { float v = row[h]; a1 += v; a2 += v*v; aw += v*ws[h]; }
        s1[tid] = a1; s2[tid] = a2; sw[tid] = aw;
    }
    __syncthreads();
    if (tid < 6) {
        float s = 0.f;
        #pragma unroll
        for (int c = 0; c < 12; c++) s += sw[tid*12 + c];
        lin[tid] = s * (1.0f/12.0f) + fcb[0];
    }
    __syncthreads();
    if (tid < CCH) {
        const int cls = tid / 12;
        float mult;
        if (cls == 0)      mult = sigmoidf_(lin[5] + lin[0]);
        else if (cls == 5) mult = 1.0f;
        else               mult = sigmoidf_(lin[5-cls] + lin[5]);
        int src = (cls == 0 || cls == 5) ? tid : tid + 12*(5 - 2*cls);
        g_part[(size_t)b*144 + tid*2 + 0] = mult * s1[src];
        g_part[(size_t)b*144 + tid*2 + 1] = mult * mult * s2[src];
        if ((tid % 12) == 0) g_mult[b*6 + cls] = mult;
    }
}

// ---------------------------------------------------------------------------
// K2: BN partial reduction + tf32 B-fragment build
// ---------------------------------------------------------------------------
__global__ void __launch_bounds__(144) k2_reduce(const float* __restrict__ convw)
{
    const int t = threadIdx.x, blk = blockIdx.x;
    if (blk < RED_BLOCKS) {
        float acc = 0.f;
        size_t base = (size_t)blk * RED_PER * 144 + t;
        #pragma unroll 8
        for (int i = 0; i < RED_PER; i++) acc += g_part[base + (size_t)i * 144];
        g_part2[blk*144 + t] = acc;
    } else {
        int idx = (blk - RED_BLOCKS) * 144 + t;
        if (idx < 3456) {
            int r  = idx & 1;
            int l  = (idx >> 1) & 31;
            int q  = idx >> 6;
            int ks = q % 9;
            int nt = q / 9;
            int n    = nt*8 + (l >> 2);
            int tap  = n >> 4;
            int oc   = n & 15;
            int chan = ks*8 + (l & 3) + 4*r;
            unsigned int val = 0u;
            if (oc < 12) val = f2tf32(convw[oc*216 + chan*3 + tap]);
            g_Bf[idx] = val;
        }
    }
}

__global__ void __launch_bounds__(72) k2b_final(
    const float* __restrict__ gamma, const float* __restrict__ beta)
{
    const int c = threadIdx.x;
    float s = 0.f, q = 0.f;
    #pragma unroll 8
    for (int i = 0; i < RED_BLOCKS; i++) {
        s += g_part2[i*144 + 2*c + 0];
        q += g_part2[i*144 + 2*c + 1];
    }
    const float inv = 1.0f / BN_COUNT;
    float mu = s*inv, var = q*inv - mu*mu;
    float scale = gamma[c] * rsqrtf(var + BN_EPS_F);
    g_ss[c] = scale;
    g_ss[72+c] = beta[c] - mu*scale;
}

// ---------------------------------------------------------------------------
// K3: persistent, double-pumped: cp.async prefetch of tile t+GRID overlaps
// copy-out/MMA/epilogue of tile t. x-copy re-reads x via LDG (L2-hot).
// ---------------------------------------------------------------------------
__global__ void __launch_bounds__(BT, 1) k3_mma(
    const float* __restrict__ x, float* __restrict__ out)
{
    extern __shared__ char smem[];
    float*        Bc   = (float*)(smem + OFF_BC);
    float*        scx  = (float*)(smem + OFF_SCX);
    int*          cpart= (int*)  (smem + OFF_XC);
    float*        mlsh = (float*)(smem + OFF_ML);     // 2 x 48
    float*        rawF = (float*)(smem + OFF_RAW);
    unsigned int* Amem = (unsigned int*)(smem + OFF_A);
    unsigned int* Bmem = (unsigned int*)(smem + OFF_B);
    float*        Dmem = (float*)(smem + OFF_D);

    const int tid  = threadIdx.x;
    const int wid  = tid >> 5;
    const int lane = tid & 31;

    const uint32_t rawS = (uint32_t)__cvta_generic_to_shared(rawF);
    const uint32_t mlS  = (uint32_t)__cvta_generic_to_shared(mlsh);

    // prologue: prefetch first tile + tables
    {
        const int t0 = blockIdx.x;
        const float4* xg = (const float4*)(x + (size_t)t0 * TB * SAMP);
        #pragma unroll
        for (int i = tid; i < TB*SAMP/4; i += BT) CP_ASYNC16(rawS + i*16, xg + i);
        if (tid < 12) CP_ASYNC16(mlS + tid*16, (const float4*)(g_mult + t0*TB*6) + tid);
        CP_COMMIT();
    }
    if (tid < 72) {
        int g = tid/12, r = tid - g*12;
        int xcls = (g == 0 || g == 5) ? g : (5 - g);
        int xc = 12*xcls + r;
        scx[tid] = g_ss[xc];
        Bc[tid]  = g_ss[72 + xc];
        cpart[tid] = (xc >> 3)*128 + (xc & 3)*4 + 2*((xc & 7) >> 2);
    }
    {
        const float4* src = (const float4*)g_Bf;
        float4* dst = (float4*)Bmem;
        #pragma unroll
        for (int i = tid; i < 864; i += BT) dst[i] = src[i];
    }
    CP_WAIT0();
    __syncthreads();

    // per-thread row identity
    const int row = tid;
    const int s = row / 36;
    const int m = row - s*36;
    const bool interior = (m >= 1) && (m <= 34);
    const int rowin = row & 15;
    const int rpart = (row >> 4)*1152 + (rowin & 7)*16 + (rowin >> 3);
    const int rsw   = ((rowin >> 1) & 3) << 2;
    const int lane_sw = (lane & 28) | ((lane & 3) ^ ((lane >> 3) & 3));

    int k = 0;
    for (int t = blockIdx.x; t < NT; t += GRID3, k++) {
        const int b0 = t * TB;
        const float* ml = mlsh + (k & 1)*48 + s*6;

        // transform rawF -> A (tf32 fragments). groups 0..5 use ml 0,4,3,2,1,5
        {
            const float* rs = rawF + s*SAMP + (m - 1);
            const float ml0 = ml[0], ml1 = ml[1], ml2 = ml[2];
            const float ml3 = ml[3], ml4 = ml[4], ml5 = ml[5];
            #pragma unroll
            for (int j = 0; j < 24; j++) {
                const int c = j;
                const float mlc = (j < 12) ? ml0 : ml4;
                float v = interior ? rs[c*HH] : 0.f;
                Amem[rpart + (cpart[c] ^ rsw)] = f2tf32(fmaxf(fmaf(scx[c]*mlc, v, Bc[c]), 0.f));
            }
            #pragma unroll
            for (int j = 0; j < 24; j++) {
                const int c = 24 + j;
                const float mlc = (j < 12) ? ml3 : ml2;
                float v = interior ? rs[c*HH] : 0.f;
                Amem[rpart + (cpart[c] ^ rsw)] = f2tf32(fmaxf(fmaf(scx[c]*mlc, v, Bc[c]), 0.f));
            }
            #pragma unroll
            for (int j = 0; j < 24; j++) {
                const int c = 48 + j;
                const float mlc = (j < 12) ? ml1 : ml5;
                float v = interior ? rs[c*HH] : 0.f;
                Amem[rpart + (cpart[c] ^ rsw)] = f2tf32(fmaxf(fmaf(scx[c]*mlc, v, Bc[c]), 0.f));
            }
        }
        __syncthreads();   // A complete; rawF free

        // prefetch next tile (overlaps everything below)
        const int tn = t + GRID3;
        if (tn < NT) {
            const float4* xg = (const float4*)(x + (size_t)tn * TB * SAMP);
            #pragma unroll
            for (int i = tid; i < TB*SAMP/4; i += BT) CP_ASYNC16(rawS + i*16, xg + i);
            if (tid < 12)
                CP_ASYNC16(mlS + ((k+1)&1)*192 + tid*16, (const float4*)(g_mult + tn*TB*6) + tid);
            CP_COMMIT();
        }

        // x-copy: LDG (L2-hot) -> out channels [0,72)
        {
            const float4* xg = (const float4*)(x + (size_t)b0 * SAMP);
            #pragma unroll 4
            for (int idx = tid; idx < TB*SAMP/4; idx += BT) {
                int ss  = idx / (SAMP/4);
                int off = idx - ss * (SAMP/4);
                ((float4*)(out + (size_t)(b0 + ss) * OSAMP))[off] = xg[idx];
            }
        }

        // MMA: warp owns m-tiles 2*wid, 2*wid+1
        float d[2][6][4];
        #pragma unroll
        for (int i = 0; i < 2; i++)
            #pragma unroll
            for (int n = 0; n < 6; n++)
                #pragma unroll
                for (int r = 0; r < 4; r++) d[i][n][r] = 0.f;
        {
            const int mt0 = wid*2, mt1 = wid*2 + 1;
            const uint4* Af = (const uint4*)Amem;
            const uint2* Bf = (const uint2*)Bmem;
            #pragma unroll
            for (int ks = 0; ks < 9; ks++) {
                uint4 a0 = Af[(mt0*9 + ks)*32 + lane_sw];
                uint4 a1 = Af[(mt1*9 + ks)*32 + lane_sw];
                #pragma unroll
                for (int nt = 0; nt < 6; nt++) {
                    uint2 b = Bf[(nt*9 + ks)*32 + lane];
                    MMAT32(d[0][nt], a0, b.x, b.y);
                    MMAT32(d[1][nt], a1, b.x, b.y);
                }
            }
        }
        __syncthreads();   // A reads done; D overlays A

        #pragma unroll
        for (int i = 0; i < 2; i++) {
            const int row0 = (wid*2 + i)*16 + (lane >> 2);
            #pragma unroll
            for (int nt = 0; nt < 6; nt++) {
                const int col = nt*8 + 2*(lane & 3);
                *(float2*)(Dmem + row0*DSTRIDE + col)       = make_float2(d[i][nt][0], d[i][nt][1]);
                *(float2*)(Dmem + (row0 + 8)*DSTRIDE + col) = make_float2(d[i][nt][2], d[i][nt][3]);
            }
        }
        __syncthreads();

        if (tid < 272) {
            const int se = tid / 34;
            const int h  = tid - se*34;
            const float* dr = Dmem + (se*36 + h)*DSTRIDE;
            float* ob = out + (size_t)(b0 + se) * OSAMP + 72*HH + h;
            #pragma unroll
            for (int oc = 0; oc < 12; oc++)
                ob[oc*HH] = dr[oc] + dr[DSTRIDE + 16 + oc] + dr[2*DSTRIDE + 32 + oc];
        }

        CP_WAIT0();        // next tile landed
        __syncthreads();   // epilogue reads done before next transform writes A
    }
}

// ---------------------------------------------------------------------------
extern "C" void kernel_launch(void* const* d_in, const int* in_sizes, int n_in,
                              void* d_out, int out_size)
{
    const float* x      = (const float*)d_in[0];
    const float* gamma  = (const float*)d_in[1];
    const float* beta   = (const float*)d_in[2];
    const float* conv_w = (const float*)d_in[3];
    const float* fc_w   = (const float*)d_in[4];
    const float* fc_b   = (const float*)d_in[5];
    float* out = (float*)d_out;

    const int B = in_sizes[0] / SAMP;   // 16384

    cudaFuncSetAttribute(k3_mma, cudaFuncAttributeMaxDynamicSharedMemorySize, SMEM_K3);

    k1_stats<<<B, 128>>>(x, fc_w, fc_b);
    k2_reduce<<<RED_BLOCKS + WB_BLOCKS, 144>>>(conv_w);
    k2b_final<<<1, 72>>>(gamma, beta);
    k3_mma<<<GRID3, BT, SMEM_K3>>>(x, out);
}

// round 16
// speedup vs baseline: 1.1887x; 1.1887x over previous
#include <cuda_runtime.h>
#include <cuda_bf16.h>
#include <math.h>
#include <cstdint>

#define BATCH   16384
#define CCH     72
#define HH      34
#define SAMP    2448
#define OSAMP   2856
#define TB      4             /* samples per conv block */
#define BT      160           /* conv block threads (5 warps, 9 m16-tiles) */
#define RED_BLOCKS 64
#define RED_PER    256
#define WB_BLOCKS  24
#define BN_COUNT   (16384.0f*34.0f)
#define BN_EPS_F   1e-5f

/* k3 smem layout (bytes) */
#define OFF_BC  0             /* 72 f  */
#define OFF_SCX 288           /* 72 f  */
#define OFF_XC  576           /* 72 i  */
#define OFF_ML  864           /* 24 f  */
#define OFF_A   1280          /* 9*9*128 u32 = 41472 B */
#define OFF_B   42752         /* 3456 u32 = 13824 B */
#define SMEM_K3 56576
#define OFF_D   OFF_A         /* D overlays A: 144 x 50 f = 28800 B */
#define DSTRIDE 50

__device__ float g_mult[BATCH*6];
__device__ float g_part[BATCH*144];
__device__ float g_part2[RED_BLOCKS*144];
__device__ float g_ss[144];
__device__ unsigned int g_Bf[3456];   /* tf32 B fragments */

__device__ __forceinline__ float sigmoidf_(float z) {
    return 1.0f / (1.0f + __expf(-z));
}
__device__ __forceinline__ unsigned int f2tf32(float v) {
    unsigned int u;
    asm("cvt.rna.tf32.f32 %0, %1;" : "=r"(u) : "f"(v));
    return u;
}

#define MMAT32(d, a, bx, by) \
    asm volatile("mma.sync.aligned.m16n8k8.row.col.f32.tf32.tf32.f32 " \
        "{%0,%1,%2,%3}, {%4,%5,%6,%7}, {%8,%9}, {%0,%1,%2,%3};" \
        : "+f"((d)[0]), "+f"((d)[1]), "+f"((d)[2]), "+f"((d)[3]) \
        : "r"((a).x), "r"((a).y), "r"((a).z), "r"((a).w), "r"(bx), "r"(by))

// ---------------------------------------------------------------------------
// K1: per-sample gates + BN partial sums + copy x into output channels [0,72)
// ---------------------------------------------------------------------------
__global__ void __launch_bounds__(128) k1_stats(
    const float* __restrict__ x, const float* __restrict__ fcw,
    const float* __restrict__ fcb, float* __restrict__ out)
{
    __shared__ float xs[SAMP];
    __shared__ float ws[HH];
    __shared__ float s1[CCH], s2[CCH], sw[CCH];
    __shared__ float lin[6];

    const int b = blockIdx.x, tid = threadIdx.x;
    const float4* xin4 = (const float4*)(x + (size_t)b * SAMP);
    float4* out4 = (float4*)(out + (size_t)b * OSAMP);
    float4* xs4 = (float4*)xs;
    #pragma unroll
    for (int i = tid; i < SAMP/4; i += 128) { float4 v = xin4[i]; xs4[i] = v; out4[i] = v; }
    if (tid < HH) ws[tid] = fcw[tid];
    __syncthreads();

    if (tid < CCH) {
        float a1 = 0.f, a2 = 0.f, aw = 0.f;
        const float* row = xs + tid * HH;
        #pragma unroll
        for (int h = 0; h < HH; h++) { float v = row[h]; a1 += v; a2 += v*v; aw += v*ws[h]; }
        s1[tid] = a1; s2[tid] = a2; sw[tid] = aw;
    }
    __syncthreads();
    if (tid < 6) {
        float s = 0.f;
        #pragma unroll
        for (int c = 0; c < 12; c++) s += sw[tid*12 + c];
        lin[tid] = s * (1.0f/12.0f) + fcb[0];
    }
    __syncthreads();
    if (tid < CCH) {
        const int cls = tid / 12;
        float mult;
        if (cls == 0)      mult = sigmoidf_(lin[5] + lin[0]);
        else if (cls == 5) mult = 1.0f;
        else               mult = sigmoidf_(lin[5-cls] + lin[5]);
        int src = (cls == 0 || cls == 5) ? tid : tid + 12*(5 - 2*cls);
        g_part[(size_t)b*144 + tid*2 + 0] = mult * s1[src];
        g_part[(size_t)b*144 + tid*2 + 1] = mult * mult * s2[src];
        if ((tid % 12) == 0) g_mult[b*6 + cls] = mult;
    }
}

// ---------------------------------------------------------------------------
// K2: BN partial reduction (blocks < 64) + tf32 B-fragment build (blocks >= 64)
// ---------------------------------------------------------------------------
__global__ void __launch_bounds__(144) k2_reduce(const float* __restrict__ convw)
{
    const int t = threadIdx.x, blk = blockIdx.x;
    if (blk < RED_BLOCKS) {
        float acc = 0.f;
        size_t base = (size_t)blk * RED_PER * 144 + t;
        #pragma unroll 8
        for (int i = 0; i < RED_PER; i++) acc += g_part[base + (size_t)i * 144];
        g_part2[blk*144 + t] = acc;
    } else {
        int idx = (blk - RED_BLOCKS) * 144 + t;
        if (idx < 3456) {
            int r  = idx & 1;
            int l  = (idx >> 1) & 31;
            int q  = idx >> 6;
            int ks = q % 9;
            int nt = q / 9;
            int n    = nt*8 + (l >> 2);
            int tap  = n >> 4;
            int oc   = n & 15;
            int chan = ks*8 + (l & 3) + 4*r;
            unsigned int val = 0u;
            if (oc < 12) val = f2tf32(convw[oc*216 + chan*3 + tap]);
            g_Bf[idx] = val;
        }
    }
}

__global__ void __launch_bounds__(72) k2b_final(
    const float* __restrict__ gamma, const float* __restrict__ beta)
{
    const int c = threadIdx.x;
    float s = 0.f, q = 0.f;
    #pragma unroll 8
    for (int i = 0; i < RED_BLOCKS; i++) {
        s += g_part2[i*144 + 2*c + 0];
        q += g_part2[i*144 + 2*c + 1];
    }
    const float inv = 1.0f / BN_COUNT;
    float mu = s*inv, var = q*inv - mu*mu;
    float scale = gamma[c] * rsqrtf(var + BN_EPS_F);
    g_ss[c] = scale;
    g_ss[72+c] = beta[c] - mu*scale;
}

// ---------------------------------------------------------------------------
// K3: 4-sample tiles, 160 threads, 4 blocks/SM.
// BN/relu -> tf32 A frags (9 m-tiles) -> mma GEMM -> tap epilogue.
// ---------------------------------------------------------------------------
__global__ void __launch_bounds__(BT, 4) k3_mma(
    const float* __restrict__ x, float* __restrict__ out)
{
    extern __shared__ char smem[];
    float*        Bc   = (float*)(smem + OFF_BC);
    float*        scx  = (float*)(smem + OFF_SCX);
    int*          cpart= (int*)  (smem + OFF_XC);
    float*        mlsh = (float*)(smem + OFF_ML);
    unsigned int* Amem = (unsigned int*)(smem + OFF_A);
    unsigned int* Bmem = (unsigned int*)(smem + OFF_B);
    float*        Dmem = (float*)(smem + OFF_D);

    const int tid  = threadIdx.x;
    const int wid  = tid >> 5;
    const int lane = tid & 31;
    const int b0   = blockIdx.x * TB;

    // per-thread row identity (build phase, rows 0..143)
    const int row = tid;
    const bool brow = (tid < TB*36);
    const int s = row / 36;
    const int m = row - s*36;
    const bool interior = brow && (m >= 1) && (m <= 34);
    const float* xr = x + (size_t)(b0 + s) * SAMP + (m - 1);

    // batch-0 loads: no table dependency, issue immediately
    float v0[24];
    #pragma unroll
    for (int j = 0; j < 24; j++) v0[j] = interior ? xr[j*HH] : 0.f;

    // tables
    if (tid < 72) {
        int g = tid/12, r = tid - g*12;
        int xcls = (g == 0 || g == 5) ? g : (5 - g);
        int xc = 12*xcls + r;
        scx[tid] = g_ss[xc];
        Bc[tid]  = g_ss[72 + xc];
        cpart[tid] = (xc >> 3)*128 + (xc & 3)*4 + 2*((xc & 7) >> 2);
    }
    if (tid < TB*6) mlsh[tid] = g_mult[b0*6 + tid];
    // B fragments -> smem
    {
        const float4* src = (const float4*)g_Bf;
        float4* dst = (float4*)Bmem;
        #pragma unroll
        for (int i = tid; i < 864; i += BT) dst[i] = src[i];
    }
    __syncthreads();

    // A build, pipelined. x-group g -> xcls mult: groups 0..5 use ml 0,4,3,2,1,5
    if (brow) {
        const int rowin = row & 15;
        const int rpart = (row >> 4)*1152 + (rowin & 7)*16 + (rowin >> 3);
        const int rsw   = ((rowin >> 1) & 3) << 2;
        const float ml0 = mlsh[s*6 + 0], ml1 = mlsh[s*6 + 1];
        const float ml2 = mlsh[s*6 + 2], ml3 = mlsh[s*6 + 3];
        const float ml4 = mlsh[s*6 + 4], ml5 = mlsh[s*6 + 5];

        float v1[24];
        #pragma unroll
        for (int j = 0; j < 24; j++) v1[j] = interior ? xr[(24 + j)*HH] : 0.f;

        #pragma unroll
        for (int j = 0; j < 24; j++) {           // g = 0, 1 -> xcls 0, 4
            const int c = j;
            const float mlc = (j < 12) ? ml0 : ml4;
            float hv = fmaxf(fmaf(scx[c]*mlc, v0[j], Bc[c]), 0.f);
            Amem[rpart + (cpart[c] ^ rsw)] = f2tf32(hv);
        }

        float v2[24];
        #pragma unroll
        for (int j = 0; j < 24; j++) v2[j] = interior ? xr[(48 + j)*HH] : 0.f;

        #pragma unroll
        for (int j = 0; j < 24; j++) {           // g = 2, 3 -> xcls 3, 2
            const int c = 24 + j;
            const float mlc = (j < 12) ? ml3 : ml2;
            float hv = fmaxf(fmaf(scx[c]*mlc, v1[j], Bc[c]), 0.f);
            Amem[rpart + (cpart[c] ^ rsw)] = f2tf32(hv);
        }
        #pragma unroll
        for (int j = 0; j < 24; j++) {           // g = 4, 5 -> xcls 1, 5
            const int c = 48 + j;
            const float mlc = (j < 12) ? ml1 : ml5;
            float hv = fmaxf(fmaf(scx[c]*mlc, v2[j], Bc[c]), 0.f);
            Amem[rpart + (cpart[c] ^ rsw)] = f2tf32(hv);
        }
    }
    __syncthreads();

    // mainloop: warps 0-3 own m-tiles {2w, 2w+1}; warp 4 owns m-tile 8
    const int lane_sw = (lane & 28) | ((lane & 3) ^ ((lane >> 3) & 3));
    const uint4* Af = (const uint4*)Amem;
    const uint2* Bf = (const uint2*)Bmem;

    float d[2][6][4];
    #pragma unroll
    for (int i = 0; i < 2; i++)
        #pragma unroll
        for (int n = 0; n < 6; n++)
            #pragma unroll
            for (int r = 0; r < 4; r++) d[i][n][r] = 0.f;

    if (wid < 4) {
        const int mt0 = wid*2, mt1 = wid*2 + 1;
        #pragma unroll
        for (int ks = 0; ks < 9; ks++) {
            uint4 a0 = Af[(mt0*9 + ks)*32 + lane_sw];
            uint4 a1 = Af[(mt1*9 + ks)*32 + lane_sw];
            #pragma unroll
            for (int nt = 0; nt < 6; nt++) {
                uint2 b = Bf[(nt*9 + ks)*32 + lane];
                MMAT32(d[0][nt], a0, b.x, b.y);
                MMAT32(d[1][nt], a1, b.x, b.y);
            }
        }
    } else {
        #pragma unroll
        for (int ks = 0; ks < 9; ks++) {
            uint4 a0 = Af[(8*9 + ks)*32 + lane_sw];
            #pragma unroll
            for (int nt = 0; nt < 6; nt++) {
                uint2 b = Bf[(nt*9 + ks)*32 + lane];
                MMAT32(d[0][nt], a0, b.x, b.y);
            }
        }
    }
    __syncthreads();   // all A reads done; D overlays A

    // store D to smem: row-major, stride 50
    {
        const int nmt = (wid < 4) ? 2 : 1;
        #pragma unroll
        for (int i = 0; i < 2; i++) {
            if (i >= nmt) break;
            const int mt   = (wid < 4) ? (wid*2 + i) : 8;
            const int row0 = mt*16 + (lane >> 2);
            #pragma unroll
            for (int nt = 0; nt < 6; nt++) {
                const int col = nt*8 + 2*(lane & 3);
                *(float2*)(Dmem + row0*DSTRIDE + col)       = make_float2(d[i][nt][0], d[i][nt][1]);
                *(float2*)(Dmem + (row0 + 8)*DSTRIDE + col) = make_float2(d[i][nt][2], d[i][nt][3]);
            }
        }
    }
    __syncthreads();

    // epilogue: out[h,oc] = D[s36+h, oc] + D[s36+h+1, 16+oc] + D[s36+h+2, 32+oc]
    if (tid < TB*34) {
        const int se = tid / 34;
        const int h  = tid - se*34;
        const float* dr = Dmem + (se*36 + h)*DSTRIDE;
        float* ob = out + (size_t)(b0 + se) * OSAMP + 72*HH + h;
        #pragma unroll
        for (int oc = 0; oc < 12; oc++) {
            float v = dr[oc] + dr[DSTRIDE + 16 + oc] + dr[2*DSTRIDE + 32 + oc];
            ob[oc*HH] = v;
        }
    }
}

// ---------------------------------------------------------------------------
extern "C" void kernel_launch(void* const* d_in, const int* in_sizes, int n_in,
                              void* d_out, int out_size)
{
    const float* x      = (const float*)d_in[0];
    const float* gamma  = (const float*)d_in[1];
    const float* beta   = (const float*)d_in[2];
    const float* conv_w = (const float*)d_in[3];
    const float* fc_w   = (const float*)d_in[4];
    const float* fc_b   = (const float*)d_in[5];
    float* out = (float*)d_out;

    const int B = in_sizes[0] / SAMP;   // 16384

    cudaFuncSetAttribute(k3_mma, cudaFuncAttributeMaxDynamicSharedMemorySize, SMEM_K3);

    k1_stats<<<B, 128>>>(x, fc_w, fc_b, out);
    k2_reduce<<<RED_BLOCKS + WB_BLOCKS, 144>>>(conv_w);
    k2b_final<<<1, 72>>>(gamma, beta);
    k3_mma<<<B / TB, BT, SMEM_K3>>>(x, out);
}

// round 17
// speedup vs baseline: 1.2624x; 1.0620x over previous
#include <cuda_runtime.h>
#include <cuda_bf16.h>
#include <math.h>
#include <cstdint>

#define BATCH   16384
#define CCH     72
#define HH      34
#define SAMP    2448
#define OSAMP   2856
#define TB      4             /* samples per conv block */
#define BT      160           /* conv block threads (5 warps, 9 m16-tiles) */
#define RED_BLOCKS 64
#define RED_PER    256
#define WB_BLOCKS  24
#define BN_COUNT   (16384.0f*34.0f)
#define BN_EPS_F   1e-5f

/* k3 smem layout (float indices) */
#define FI_BC    0             /* 72 f  */
#define FI_XC    72            /* 72 i  */
#define FI_COMB  144           /* 288 f */
#define FI_A     448           /* align 128B: 448*4 = 1792 */
#define SMEM_K3  (448*4 + 41472)   /* 43264 B */
#define DSTRIDE 50             /* D overlays A: 144 x 50 f */

__device__ float g_mult[BATCH*6];
__device__ float g_part[BATCH*144];
__device__ float g_part2[RED_BLOCKS*144];
__device__ float g_ss[144];
__device__ unsigned int g_Bf[3456];   /* tf32 B fragments */

__device__ __forceinline__ float sigmoidf_(float z) {
    return 1.0f / (1.0f + __expf(-z));
}
__device__ __forceinline__ unsigned int f2tf32(float v) {
    unsigned int u;
    asm("cvt.rna.tf32.f32 %0, %1;" : "=r"(u) : "f"(v));
    return u;
}

#define MMAT32(d, a, bx, by) \
    asm volatile("mma.sync.aligned.m16n8k8.row.col.f32.tf32.tf32.f32 " \
        "{%0,%1,%2,%3}, {%4,%5,%6,%7}, {%8,%9}, {%0,%1,%2,%3};" \
        : "+f"((d)[0]), "+f"((d)[1]), "+f"((d)[2]), "+f"((d)[3]) \
        : "r"((a).x), "r"((a).y), "r"((a).z), "r"((a).w), "r"(bx), "r"(by))

// ---------------------------------------------------------------------------
// K1: per-sample gates + BN partial sums + copy x into output channels [0,72)
// ---------------------------------------------------------------------------
__global__ void __launch_bounds__(128) k1_stats(
    const float* __restrict__ x, const float* __restrict__ fcw,
    const float* __restrict__ fcb, float* __restrict__ out)
{
    __shared__ float xs[SAMP];
    __shared__ float ws[HH];
    __shared__ float s1[CCH], s2[CCH], sw[CCH];
    __shared__ float lin[6];

    const int b = blockIdx.x, tid = threadIdx.x;
    const float4* xin4 = (const float4*)(x + (size_t)b * SAMP);
    float4* out4 = (float4*)(out + (size_t)b * OSAMP);
    float4* xs4 = (float4*)xs;
    #pragma unroll
    for (int i = tid; i < SAMP/4; i += 128) { float4 v = xin4[i]; xs4[i] = v; out4[i] = v; }
    if (tid < HH) ws[tid] = fcw[tid];
    __syncthreads();

    if (tid < CCH) {
        float a1 = 0.f, a2 = 0.f, aw = 0.f;
        const float* row = xs + tid * HH;
        #pragma unroll
        for (int h = 0; h < HH; h++) { float v = row[h]; a1 += v; a2 += v*v; aw += v*ws[h]; }
        s1[tid] = a1; s2[tid] = a2; sw[tid] = aw;
    }
    __syncthreads();
    if (tid < 6) {
        float s = 0.f;
        #pragma unroll
        for (int c = 0; c < 12; c++) s += sw[tid*12 + c];
        lin[tid] = s * (1.0f/12.0f) + fcb[0];
    }
    __syncthreads();
    if (tid < CCH) {
        const int cls = tid / 12;
        float mult;
        if (cls == 0)      mult = sigmoidf_(lin[5] + lin[0]);
        else if (cls == 5) mult = 1.0f;
        else               mult = sigmoidf_(lin[5-cls] + lin[5]);
        int src = (cls == 0 || cls == 5) ? tid : tid + 12*(5 - 2*cls);
        g_part[(size_t)b*144 + tid*2 + 0] = mult * s1[src];
        g_part[(size_t)b*144 + tid*2 + 1] = mult * mult * s2[src];
        if ((tid % 12) == 0) g_mult[b*6 + cls] = mult;
    }
}

// ---------------------------------------------------------------------------
// K2: BN partial reduction (blocks < 64) + tf32 B-fragment build (blocks >= 64)
// ---------------------------------------------------------------------------
__global__ void __launch_bounds__(144) k2_reduce(const float* __restrict__ convw)
{
    const int t = threadIdx.x, blk = blockIdx.x;
    if (blk < RED_BLOCKS) {
        float acc = 0.f;
        size_t base = (size_t)blk * RED_PER * 144 + t;
        #pragma unroll 8
        for (int i = 0; i < RED_PER; i++) acc += g_part[base + (size_t)i * 144];
        g_part2[blk*144 + t] = acc;
    } else {
        int idx = (blk - RED_BLOCKS) * 144 + t;
        if (idx < 3456) {
            int r  = idx & 1;
            int l  = (idx >> 1) & 31;
            int q  = idx >> 6;
            int ks = q % 9;
            int nt = q / 9;
            int n    = nt*8 + (l >> 2);
            int tap  = n >> 4;
            int oc   = n & 15;
            int chan = ks*8 + (l & 3) + 4*r;
            unsigned int val = 0u;
            if (oc < 12) val = f2tf32(convw[oc*216 + chan*3 + tap]);
            g_Bf[idx] = val;
        }
    }
}

__global__ void __launch_bounds__(72) k2b_final(
    const float* __restrict__ gamma, const float* __restrict__ beta)
{
    const int c = threadIdx.x;
    float s = 0.f, q = 0.f;
    #pragma unroll 8
    for (int i = 0; i < RED_BLOCKS; i++) {
        s += g_part2[i*144 + 2*c + 0];
        q += g_part2[i*144 + 2*c + 1];
    }
    const float inv = 1.0f / BN_COUNT;
    float mu = s*inv, var = q*inv - mu*mu;
    float scale = gamma[c] * rsqrtf(var + BN_EPS_F);
    g_ss[c] = scale;
    g_ss[72+c] = beta[c] - mu*scale;
}

// ---------------------------------------------------------------------------
// K3: 4-sample tiles, 160 threads, 5 blocks/SM (80-reg cap).
// B fragments read from global (L1-hot); comb table built straight from globals.
// ---------------------------------------------------------------------------
__global__ void __launch_bounds__(BT, 5) k3_mma(
    const float* __restrict__ x, float* __restrict__ out)
{
    extern __shared__ float smf[];
    float*        Bc   = smf + FI_BC;
    int*          cpart= (int*)(smf + FI_XC);
    float*        comb = smf + FI_COMB;            // [s][c] combined scale
    unsigned int* Amem = (unsigned int*)(smf + FI_A);
    float*        Dmem = (float*)Amem;             // D overlays A

    const int tid  = threadIdx.x;
    const int wid  = tid >> 5;
    const int lane = tid & 31;
    const int b0   = blockIdx.x * TB;

    // per-thread row identity (build phase, rows 0..143)
    const int row = tid;
    const bool brow = (tid < TB*36);
    const int s = row / 36;
    const int m = row - s*36;
    const bool interior = brow && (m >= 1) && (m <= 34);
    const float* xr = x + (size_t)(b0 + s) * SAMP + (m - 1);

    // batch-0 loads: no table dependency, issue immediately
    float v0[24];
    #pragma unroll
    for (int j = 0; j < 24; j++) v0[j] = interior ? xr[j*HH] : 0.f;

    // tables (straight from globals; tiny, L2-hot)
    if (tid < 72) {
        int g = tid/12, r = tid - g*12;
        int xcls = (g == 0 || g == 5) ? g : (5 - g);
        int xc = 12*xcls + r;
        Bc[tid]    = g_ss[72 + xc];
        cpart[tid] = (xc >> 3)*128 + (xc & 3)*4 + 2*((xc & 7) >> 2);
    }
    #pragma unroll
    for (int i = tid; i < TB*72; i += BT) {
        int ss = i / 72, c = i - ss*72;
        int g = c/12, r = c - g*12;
        int xcls = (g == 0 || g == 5) ? g : (5 - g);
        int xc = 12*xcls + r;
        comb[i] = g_ss[xc] * g_mult[(b0 + ss)*6 + xcls];
    }
    __syncthreads();

    // A build, pipelined (3 x 24-channel batches)
    if (brow) {
        const int rowin = row & 15;
        const int rpart = (row >> 4)*1152 + (rowin & 7)*16 + (rowin >> 3);
        const int rsw   = ((rowin >> 1) & 3) << 2;
        const float* cb = comb + s*72;

        float v1[24];
        #pragma unroll
        for (int j = 0; j < 24; j++) v1[j] = interior ? xr[(24 + j)*HH] : 0.f;

        #pragma unroll
        for (int j = 0; j < 24; j++) {
            const int c = j;
            float hv = fmaxf(fmaf(cb[c], v0[j], Bc[c]), 0.f);
            Amem[rpart + (cpart[c] ^ rsw)] = f2tf32(hv);
        }

        float v2[24];
        #pragma unroll
        for (int j = 0; j < 24; j++) v2[j] = interior ? xr[(48 + j)*HH] : 0.f;

        #pragma unroll
        for (int j = 0; j < 24; j++) {
            const int c = 24 + j;
            float hv = fmaxf(fmaf(cb[c], v1[j], Bc[c]), 0.f);
            Amem[rpart + (cpart[c] ^ rsw)] = f2tf32(hv);
        }
        #pragma unroll
        for (int j = 0; j < 24; j++) {
            const int c = 48 + j;
            float hv = fmaxf(fmaf(cb[c], v2[j], Bc[c]), 0.f);
            Amem[rpart + (cpart[c] ^ rsw)] = f2tf32(hv);
        }
    }
    __syncthreads();

    // mainloop: warps 0-3 own m-tiles {2w, 2w+1}; warp 4 owns m-tile 8.
    // B fragments via LDG (g_Bf is L1/L2-resident).
    const int lane_sw = (lane & 28) | ((lane & 3) ^ ((lane >> 3) & 3));
    const uint4* Af = (const uint4*)Amem;
    const uint2* Bg = (const uint2*)g_Bf;

    float d[2][6][4];
    #pragma unroll
    for (int i = 0; i < 2; i++)
        #pragma unroll
        for (int n = 0; n < 6; n++)
            #pragma unroll
            for (int r = 0; r < 4; r++) d[i][n][r] = 0.f;

    if (wid < 4) {
        const int mt0 = wid*2, mt1 = wid*2 + 1;
        #pragma unroll
        for (int ks = 0; ks < 9; ks++) {
            uint4 a0 = Af[(mt0*9 + ks)*32 + lane_sw];
            uint4 a1 = Af[(mt1*9 + ks)*32 + lane_sw];
            #pragma unroll
            for (int nt = 0; nt < 6; nt++) {
                uint2 b = Bg[(nt*9 + ks)*32 + lane];
                MMAT32(d[0][nt], a0, b.x, b.y);
                MMAT32(d[1][nt], a1, b.x, b.y);
            }
        }
    } else {
        #pragma unroll
        for (int ks = 0; ks < 9; ks++) {
            uint4 a0 = Af[(8*9 + ks)*32 + lane_sw];
            #pragma unroll
            for (int nt = 0; nt < 6; nt++) {
                uint2 b = Bg[(nt*9 + ks)*32 + lane];
                MMAT32(d[0][nt], a0, b.x, b.y);
            }
        }
    }
    __syncthreads();   // all A reads done; D overlays A

    // store D to smem: row-major, stride 50
    {
        const int nmt = (wid < 4) ? 2 : 1;
        #pragma unroll
        for (int i = 0; i < 2; i++) {
            if (i >= nmt) break;
            const int mt   = (wid < 4) ? (wid*2 + i) : 8;
            const int row0 = mt*16 + (lane >> 2);
            #pragma unroll
            for (int nt = 0; nt < 6; nt++) {
                const int col = nt*8 + 2*(lane & 3);
                *(float2*)(Dmem + row0*DSTRIDE + col)       = make_float2(d[i][nt][0], d[i][nt][1]);
                *(float2*)(Dmem + (row0 + 8)*DSTRIDE + col) = make_float2(d[i][nt][2], d[i][nt][3]);
            }
        }
    }
    __syncthreads();

    // epilogue: out[h,oc] = D[s36+h, oc] + D[s36+h+1, 16+oc] + D[s36+h+2, 32+oc]
    if (tid < TB*34) {
        const int se = tid / 34;
        const int h  = tid - se*34;
        const float* dr = Dmem + (se*36 + h)*DSTRIDE;
        float* ob = out + (size_t)(b0 + se) * OSAMP + 72*HH + h;
        #pragma unroll
        for (int oc = 0; oc < 12; oc++) {
            float v = dr[oc] + dr[DSTRIDE + 16 + oc] + dr[2*DSTRIDE + 32 + oc];
            ob[oc*HH] = v;
        }
    }
}

// ---------------------------------------------------------------------------
extern "C" void kernel_launch(void* const* d_in, const int* in_sizes, int n_in,
                              void* d_out, int out_size)
{
    const float* x      = (const float*)d_in[0];
    const float* gamma  = (const float*)d_in[1];
    const float* beta   = (const float*)d_in[2];
    const float* conv_w = (const float*)d_in[3];
    const float* fc_w   = (const float*)d_in[4];
    const float* fc_b   = (const float*)d_in[5];
    float* out = (float*)d_out;

    const int B = in_sizes[0] / SAMP;   // 16384

    cudaFuncSetAttribute(k3_mma, cudaFuncAttributeMaxDynamicSharedMemorySize, SMEM_K3);

    k1_stats<<<B, 128>>>(x, fc_w, fc_b, out);
    k2_reduce<<<RED_BLOCKS + WB_BLOCKS, 144>>>(conv_w);
    k2b_final<<<1, 72>>>(gamma, beta);
    k3_mma<<<B / TB, BT, SMEM_K3>>>(x, out);
}